// round 2
// baseline (speedup 1.0000x reference)
#include <cuda_runtime.h>
#include <math.h>

#define RESN   320
#define MTRAJ  25600
#define NB     16
#define OSN    400
#define GL     8

#define BETA_F  6.99665877f      /* pi*sqrt(4.96) */
#define BETA2_F 48.9532378f      /* pi^2*4.96 */

/* scratch: gridded k-space (complex) and row-pass intermediate (complex, transposed) */
__device__ __align__(16) float g_grid[NB * OSN * OSN * 2];
__device__ __align__(16) float g_T1[NB * RESN * OSN * 2];

/* ---------------- Bessel I0 (A&S 9.8.1 / 9.8.2) ---------------- */
__device__ __forceinline__ float i0f_dev(float x) {
    if (x < 3.75f) {
        float t = x * (1.0f / 3.75f);
        t *= t;
        return 1.0f + t * (3.5156229f + t * (3.0899424f + t * (1.2067492f
             + t * (0.2659732f + t * (0.0360768f + t * 0.0045813f)))));
    } else {
        float t = 3.75f / x;
        float p = 0.39894228f + t * (0.01328592f + t * (0.00225319f + t * (-0.00157565f
                + t * (0.00916281f + t * (-0.02057706f + t * (0.02635537f
                + t * (-0.01647633f + t * 0.00392377f)))))));
        return expf(x) * rsqrtf(x) * p;
    }
}

__device__ __forceinline__ float kbw(float delta) {
    float u  = delta * 0.5f;                 /* delta / half, half = WIDTH/2 = 2 */
    float tt = fmaxf(1.0f - u * u, 0.0f);
    return i0f_dev(BETA_F * sqrtf(tt)) * 0.25f;   /* / WIDTH */
}

__device__ __forceinline__ float apodf(int i) {
    float d = (float)(i - 160) * 0.0314159265f;   /* pi*WIDTH*(i-n/2)/os_n = pi/100 */
    float a = sqrtf(fmaxf(BETA2_F - d * d, 1e-12f));
    return a / sinhf(a);
}

/* ---------------- kernel 1: zero the scatter grid ---------------- */
__global__ void zero_grid_kernel() {
    int i = blockIdx.x * blockDim.x + threadIdx.x;
    if (i < NB * OSN * OSN * 2 / 4)
        ((float4*)g_grid)[i] = make_float4(0.f, 0.f, 0.f, 0.f);
}

/* ------- kernel 2: bilinear sample + Kaiser-Bessel scatter ------- */
__global__ void grid_scatter_kernel(const float* __restrict__ ksp,
                                    const float* __restrict__ traj) {
    int idx = blockIdx.x * blockDim.x + threadIdx.x;
    if (idx >= NB * MTRAJ) return;
    int b = idx & (NB - 1);
    int m = idx >> 4;

    float t0 = traj[2 * m + 0];
    float t1 = traj[2 * m + 1];

    /* bilinear sample of (2-ch) k-space image: t0 -> x, t1 -> y */
    float px = (t0 * (1.0f / 160.0f) + 1.0f) * 0.5f * 319.0f;
    float py = (t1 * (1.0f / 160.0f) + 1.0f) * 0.5f * 319.0f;
    float x0f = floorf(px), y0f = floorf(py);
    float wx1 = px - x0f,   wy1 = py - y0f;
    int   x0  = (int)x0f,   y0  = (int)y0f;

    const float* img = ksp + (size_t)b * (RESN * RESN * 2);
    float yr = 0.f, yi = 0.f;
#pragma unroll
    for (int dy = 0; dy < 2; dy++) {
#pragma unroll
        for (int dx = 0; dx < 2; dx++) {
            int  xi  = x0 + dx, yv = y0 + dy;
            float w  = (dx ? wx1 : 1.0f - wx1) * (dy ? wy1 : 1.0f - wy1);
            bool inb = (xi >= 0) && (xi < RESN) && (yv >= 0) && (yv < RESN);
            int  xc  = min(max(xi, 0), RESN - 1);
            int  yc  = min(max(yv, 0), RESN - 1);
            float2 v = *(const float2*)(img + ((size_t)yc * RESN + xc) * 2);
            float wm = inb ? w : 0.0f;
            yr += v.x * wm;
            yi += v.y * wm;
        }
    }

    /* KB gridding: coord column 0 -> grid ROW (y), column 1 -> grid COL (x) */
    float cy = t0 * 1.25f + 200.0f;
    float cx = t1 * 1.25f + 200.0f;
    int sy = (int)ceilf(cy - 2.0f);
    int sx = (int)ceilf(cx - 2.0f);

    float wy[4], wx[4];
    int   iy[4], ix[4];
#pragma unroll
    for (int j = 0; j < 4; j++) {
        wy[j] = kbw(cy - (float)(sy + j));
        wx[j] = kbw(cx - (float)(sx + j));
        int a = sy + j; if (a < 0) a += OSN; if (a >= OSN) a -= OSN; iy[j] = a;
        int c = sx + j; if (c < 0) c += OSN; if (c >= OSN) c -= OSN; ix[j] = c;
    }

    float* gb = g_grid + (size_t)b * (OSN * OSN * 2);
#pragma unroll
    for (int jy = 0; jy < 4; jy++) {
#pragma unroll
        for (int jx = 0; jx < 4; jx++) {
            float w = wy[jy] * wx[jx];
            float* cell = gb + ((size_t)iy[jy] * OSN + ix[jx]) * 2;
            atomicAdd(cell,     yr * w);
            atomicAdd(cell + 1, yi * w);
        }
    }
}

/* --------------- centered 400-pt DFT, Cooley-Tukey 20x20 ---------------
   out[t] = sum_m x[m] * E[(m-200)(t-160) mod 400],  E[p] = exp(+2i*pi*p/400)
   m = 20*m1 + m2 :
     stage1: S[m2][q] = sum_m1 x[20*m1+m2] * E[20*((m1*q) mod 20)], q = t mod 20
     stage2: out[t]   = sum_m2 S[m2][t mod 20] * E[((m2-200)(t-160)) mod 400]
   per-m2 exponent step: (t-160) mod 400 = t + 240;  init (t odd ? 200 : 0)
------------------------------------------------------------------------ */

__global__ void row_dft_kernel() {
    extern __shared__ float2 shm[];
    float2* xs = shm;                 /* GL * 400 */
    float2* S  = shm + GL * OSN;      /* GL * 400 */
    float2* E  = shm + 2 * GL * OSN;  /* 400 */

    int t  = threadIdx.x;                       /* 0..399 */
    int b  = blockIdx.x / (OSN / GL);
    int y0 = (blockIdx.x % (OSN / GL)) * GL;

    const float2* gp = ((const float2*)g_grid) + ((size_t)b * OSN + y0) * OSN;
#pragma unroll
    for (int l = 0; l < GL; l++) xs[l * OSN + t] = gp[(size_t)l * OSN + t];
    {
        float sv, cv;
        sincospif((float)t * (1.0f / 200.0f), &sv, &cv);
        E[t] = make_float2(cv, sv);
    }
    __syncthreads();

    /* stage 1 */
    {
        int m2 = t % 20, q = t / 20;
        float2 acc[GL];
#pragma unroll
        for (int l = 0; l < GL; l++) acc[l] = make_float2(0.f, 0.f);
        int k = 0;
#pragma unroll
        for (int m1 = 0; m1 < 20; m1++) {
            float2 tw = E[k * 20];
            k += q; if (k >= 20) k -= 20;
            const float2* xp = xs + 20 * m1 + m2;
#pragma unroll
            for (int l = 0; l < GL; l++) {
                float2 a = xp[l * OSN];
                acc[l].x = fmaf(a.x, tw.x, fmaf(-a.y, tw.y, acc[l].x));
                acc[l].y = fmaf(a.x, tw.y, fmaf( a.y, tw.x, acc[l].y));
            }
        }
#pragma unroll
        for (int l = 0; l < GL; l++) S[l * OSN + m2 * 20 + q] = acc[l];
    }
    __syncthreads();

    /* stage 2 + transposed store T1[b][x_out][y] */
    if (t < RESN) {
        int q = t % 20;
        int p = (t & 1) ? 200 : 0;
        int s = t + 240; if (s >= OSN) s -= OSN;
        float2 acc[GL];
#pragma unroll
        for (int l = 0; l < GL; l++) acc[l] = make_float2(0.f, 0.f);
#pragma unroll
        for (int m2 = 0; m2 < 20; m2++) {
            float2 tw = E[p];
            p += s; if (p >= OSN) p -= OSN;
            const float2* sp = S + m2 * 20 + q;
#pragma unroll
            for (int l = 0; l < GL; l++) {
                float2 a = sp[l * OSN];
                acc[l].x = fmaf(a.x, tw.x, fmaf(-a.y, tw.y, acc[l].x));
                acc[l].y = fmaf(a.x, tw.y, fmaf( a.y, tw.x, acc[l].y));
            }
        }
        float4* Tv = (float4*)(((float2*)g_T1) + ((size_t)b * RESN + t) * OSN + y0);
        Tv[0] = make_float4(acc[0].x, acc[0].y, acc[1].x, acc[1].y);
        Tv[1] = make_float4(acc[2].x, acc[2].y, acc[3].x, acc[3].y);
        Tv[2] = make_float4(acc[4].x, acc[4].y, acc[5].x, acc[5].y);
        Tv[3] = make_float4(acc[6].x, acc[6].y, acc[7].x, acc[7].y);
    }
}

__global__ void col_dft_kernel(float* __restrict__ out) {
    extern __shared__ float2 shm[];
    float2* xs   = shm;
    float2* S    = shm + GL * OSN;
    float2* E    = shm + 2 * GL * OSN;
    float*  apod = (float*)(shm + 2 * GL * OSN + OSN);

    int t  = threadIdx.x;
    int b  = blockIdx.x / (RESN / GL);
    int x0 = (blockIdx.x % (RESN / GL)) * GL;

    const float2* Tp = ((const float2*)g_T1) + ((size_t)b * RESN + x0) * OSN;
#pragma unroll
    for (int l = 0; l < GL; l++) xs[l * OSN + t] = Tp[(size_t)l * OSN + t];
    {
        float sv, cv;
        sincospif((float)t * (1.0f / 200.0f), &sv, &cv);
        E[t] = make_float2(cv, sv);
    }
    if (t < RESN) apod[t] = apodf(t);
    __syncthreads();

    /* stage 1 */
    {
        int m2 = t % 20, q = t / 20;
        float2 acc[GL];
#pragma unroll
        for (int l = 0; l < GL; l++) acc[l] = make_float2(0.f, 0.f);
        int k = 0;
#pragma unroll
        for (int m1 = 0; m1 < 20; m1++) {
            float2 tw = E[k * 20];
            k += q; if (k >= 20) k -= 20;
            const float2* xp = xs + 20 * m1 + m2;
#pragma unroll
            for (int l = 0; l < GL; l++) {
                float2 a = xp[l * OSN];
                acc[l].x = fmaf(a.x, tw.x, fmaf(-a.y, tw.y, acc[l].x));
                acc[l].y = fmaf(a.x, tw.y, fmaf( a.y, tw.x, acc[l].y));
            }
        }
#pragma unroll
        for (int l = 0; l < GL; l++) S[l * OSN + m2 * 20 + q] = acc[l];
    }
    __syncthreads();

    /* stage 2 + apodization + final store */
    if (t < RESN) {
        int q = t % 20;
        int p = (t & 1) ? 200 : 0;
        int s = t + 240; if (s >= OSN) s -= OSN;
        float2 acc[GL];
#pragma unroll
        for (int l = 0; l < GL; l++) acc[l] = make_float2(0.f, 0.f);
#pragma unroll
        for (int m2 = 0; m2 < 20; m2++) {
            float2 tw = E[p];
            p += s; if (p >= OSN) p -= OSN;
            const float2* sp = S + m2 * 20 + q;
#pragma unroll
            for (int l = 0; l < GL; l++) {
                float2 a = sp[l * OSN];
                acc[l].x = fmaf(a.x, tw.x, fmaf(-a.y, tw.y, acc[l].x));
                acc[l].y = fmaf(a.x, tw.y, fmaf( a.y, tw.x, acc[l].y));
            }
        }
        float fy = apod[t] * (1.0f / 320.0f);
        float fa[GL];
#pragma unroll
        for (int l = 0; l < GL; l++) fa[l] = fy * apod[x0 + l];

        float* po = out + (((size_t)b * 2 * RESN + t) * RESN + x0);
        float4 r0 = make_float4(acc[0].x * fa[0], acc[1].x * fa[1],
                                acc[2].x * fa[2], acc[3].x * fa[3]);
        float4 r1 = make_float4(acc[4].x * fa[4], acc[5].x * fa[5],
                                acc[6].x * fa[6], acc[7].x * fa[7]);
        ((float4*)po)[0] = r0;
        ((float4*)po)[1] = r1;

        float* pi = po + RESN * RESN;   /* channel 1 = imag */
        float4 i0v = make_float4(acc[0].y * fa[0], acc[1].y * fa[1],
                                 acc[2].y * fa[2], acc[3].y * fa[3]);
        float4 i1v = make_float4(acc[4].y * fa[4], acc[5].y * fa[5],
                                 acc[6].y * fa[6], acc[7].y * fa[7]);
        ((float4*)pi)[0] = i0v;
        ((float4*)pi)[1] = i1v;
    }
}

extern "C" void kernel_launch(void* const* d_in, const int* in_sizes, int n_in,
                              void* d_out, int out_size) {
    const float* ksp  = (const float*)d_in[0];
    const float* traj = (const float*)d_in[1];
    float* out = (float*)d_out;

    const int SMEM_ROW = (2 * GL * OSN + OSN) * (int)sizeof(float2);          /* 54400 B */
    const int SMEM_COL = SMEM_ROW + RESN * (int)sizeof(float);                /* 55680 B */

    cudaFuncSetAttribute(row_dft_kernel, cudaFuncAttributeMaxDynamicSharedMemorySize, SMEM_ROW);
    cudaFuncSetAttribute(col_dft_kernel, cudaFuncAttributeMaxDynamicSharedMemorySize, SMEM_COL);

    zero_grid_kernel<<<(NB * OSN * OSN * 2 / 4 + 255) / 256, 256>>>();
    grid_scatter_kernel<<<(NB * MTRAJ + 255) / 256, 256>>>(ksp, traj);
    row_dft_kernel<<<NB * (OSN / GL), OSN, SMEM_ROW>>>();
    col_dft_kernel<<<NB * (RESN / GL), OSN, SMEM_COL>>>(out);
}

// round 3
// speedup vs baseline: 1.7038x; 1.7038x over previous
#include <cuda_runtime.h>
#include <math.h>

#define RESN   320
#define MTRAJ  25600
#define NB     16
#define OSN    400
#define GL     8

#define BETA_F  6.99665877f      /* pi*sqrt(4.96) */
#define BETA2_F 48.9532378f      /* pi^2*4.96 */

/* scratch: gridded k-space (complex) and row-pass intermediate (complex, transposed) */
__device__ __align__(16) float g_grid[NB * OSN * OSN * 2];
__device__ __align__(16) float g_T1[NB * RESN * OSN * 2];

/* ---------------- Bessel I0 (A&S 9.8.1 / 9.8.2) ---------------- */
__device__ __forceinline__ float i0f_dev(float x) {
    if (x < 3.75f) {
        float t = x * (1.0f / 3.75f);
        t *= t;
        return 1.0f + t * (3.5156229f + t * (3.0899424f + t * (1.2067492f
             + t * (0.2659732f + t * (0.0360768f + t * 0.0045813f)))));
    } else {
        float t = 3.75f / x;
        float p = 0.39894228f + t * (0.01328592f + t * (0.00225319f + t * (-0.00157565f
                + t * (0.00916281f + t * (-0.02057706f + t * (0.02635537f
                + t * (-0.01647633f + t * 0.00392377f)))))));
        return expf(x) * rsqrtf(x) * p;
    }
}

__device__ __forceinline__ float kbw(float delta) {
    float u  = delta * 0.5f;
    float tt = fmaxf(1.0f - u * u, 0.0f);
    return i0f_dev(BETA_F * sqrtf(tt)) * 0.25f;
}

__device__ __forceinline__ float apodf(int i) {
    float d = (float)(i - 160) * 0.0314159265f;
    float a = sqrtf(fmaxf(BETA2_F - d * d, 1e-12f));
    return a / sinhf(a);
}

__device__ __forceinline__ void red_add_v2(float* p, float a, float b) {
    asm volatile("red.global.add.v2.f32 [%0], {%1, %2};"
                 :: "l"(p), "f"(a), "f"(b) : "memory");
}

/* ---------------- kernel 1: zero the scatter grid ---------------- */
__global__ void zero_grid_kernel() {
    int i = blockIdx.x * blockDim.x + threadIdx.x;
    if (i < NB * OSN * OSN * 2 / 4)
        ((float4*)g_grid)[i] = make_float4(0.f, 0.f, 0.f, 0.f);
}

/* ------- kernel 2: bilinear sample + Kaiser-Bessel scatter ------- */
__global__ void grid_scatter_kernel(const float* __restrict__ ksp,
                                    const float* __restrict__ traj) {
    int idx = blockIdx.x * blockDim.x + threadIdx.x;
    if (idx >= NB * MTRAJ) return;
    int b = idx & (NB - 1);
    int m = idx >> 4;

    float t0 = traj[2 * m + 0];
    float t1 = traj[2 * m + 1];

    /* bilinear sample of (2-ch) k-space image: t0 -> x, t1 -> y */
    float px = (t0 * (1.0f / 160.0f) + 1.0f) * 0.5f * 319.0f;
    float py = (t1 * (1.0f / 160.0f) + 1.0f) * 0.5f * 319.0f;
    float x0f = floorf(px), y0f = floorf(py);
    float wx1 = px - x0f,   wy1 = py - y0f;
    int   x0  = (int)x0f,   y0  = (int)y0f;

    const float* img = ksp + (size_t)b * (RESN * RESN * 2);
    float yr = 0.f, yi = 0.f;
#pragma unroll
    for (int dy = 0; dy < 2; dy++) {
#pragma unroll
        for (int dx = 0; dx < 2; dx++) {
            int  xi  = x0 + dx, yv = y0 + dy;
            float w  = (dx ? wx1 : 1.0f - wx1) * (dy ? wy1 : 1.0f - wy1);
            bool inb = (xi >= 0) && (xi < RESN) && (yv >= 0) && (yv < RESN);
            int  xc  = min(max(xi, 0), RESN - 1);
            int  yc  = min(max(yv, 0), RESN - 1);
            float2 v = *(const float2*)(img + ((size_t)yc * RESN + xc) * 2);
            float wm = inb ? w : 0.0f;
            yr += v.x * wm;
            yi += v.y * wm;
        }
    }

    /* KB gridding: coord column 0 -> grid ROW (y), column 1 -> grid COL (x) */
    float cy = t0 * 1.25f + 200.0f;
    float cx = t1 * 1.25f + 200.0f;
    int sy = (int)ceilf(cy - 2.0f);
    int sx = (int)ceilf(cx - 2.0f);

    float wy[4], wx[4];
    int   iy[4], ix[4];
#pragma unroll
    for (int j = 0; j < 4; j++) {
        wy[j] = kbw(cy - (float)(sy + j));
        wx[j] = kbw(cx - (float)(sx + j));
        int a = sy + j; if (a < 0) a += OSN; if (a >= OSN) a -= OSN; iy[j] = a;
        int c = sx + j; if (c < 0) c += OSN; if (c >= OSN) c -= OSN; ix[j] = c;
    }

    float* gb = g_grid + (size_t)b * (OSN * OSN * 2);
#pragma unroll
    for (int jy = 0; jy < 4; jy++) {
#pragma unroll
        for (int jx = 0; jx < 4; jx++) {
            float w = wy[jy] * wx[jx];
            float* cell = gb + ((size_t)iy[jy] * OSN + ix[jx]) * 2;
            red_add_v2(cell, yr * w, yi * w);
        }
    }
}

/* --------------- centered 400-pt DFT, Cooley-Tukey 20x20 ---------------
   out[t] = sum_m x[m] * E[(m-200)(t-160) mod 400],  E[p] = exp(+2i*pi*p/400)
   m = 20*m1 + m2 :
     stage1: S[m2*20+q] = sum_m1 x[20*m1+m2] * exp(2i*pi*m1*q/20)
     stage2: out[t]     = sum_m2 S[m2*20 + (t%20)] * E[((m2-200)(t-160)) mod 400]
   Thread maps chosen so all shared-memory data reads are warp-broadcast;
   twiddles generated by register rotation recurrences.
------------------------------------------------------------------------ */

__device__ __forceinline__ float2 cmul(float2 a, float2 b) {
    return make_float2(fmaf(a.x, b.x, -a.y * b.y), fmaf(a.x, b.y, a.y * b.x));
}

__global__ void row_dft_kernel() {
    extern __shared__ float2 shm[];
    float2* xs = shm;                 /* GL * 400 */
    float2* S  = shm + GL * OSN;      /* GL * 400 */
    float2* E  = shm + 2 * GL * OSN;  /* 400 */

    int t  = threadIdx.x;                       /* 0..399 */
    int b  = blockIdx.x / (OSN / GL);
    int y0 = (blockIdx.x % (OSN / GL)) * GL;

    const float2* gp = ((const float2*)g_grid) + ((size_t)b * OSN + y0) * OSN;
#pragma unroll
    for (int l = 0; l < GL; l++) xs[l * OSN + t] = gp[(size_t)l * OSN + t];
    {
        float sv, cv;
        sincospif((float)t * (1.0f / 200.0f), &sv, &cv);
        E[t] = make_float2(cv, sv);
    }
    __syncthreads();

    /* stage 1: thread (m2 = t/20, q = t%20) -> S[t] ; xs reads broadcast */
    {
        int m2 = t / 20, q = t % 20;
        float2 acc[GL];
#pragma unroll
        for (int l = 0; l < GL; l++) acc[l] = make_float2(0.f, 0.f);
        float2 w    = make_float2(1.f, 0.f);
        float2 step = E[20 * q];
        const float2* xp = xs + m2;
#pragma unroll
        for (int m1 = 0; m1 < 20; m1++) {
#pragma unroll
            for (int l = 0; l < GL; l++) {
                float2 a = xp[l * OSN + 20 * m1];
                acc[l].x = fmaf(a.x, w.x, fmaf(-a.y, w.y, acc[l].x));
                acc[l].y = fmaf(a.x, w.y, fmaf( a.y, w.x, acc[l].y));
            }
            w = cmul(w, step);
        }
#pragma unroll
        for (int l = 0; l < GL; l++) S[l * OSN + t] = acc[l];
    }
    __syncthreads();

    /* stage 2: thread (q2 = t/16, j = t%16) -> out column tout = 20*j + q2 ;
       S reads broadcast, twiddle by rotation recurrence */
    if (t < RESN) {
        int q2 = t / 16, j = t & 15;
        int tout = 20 * j + q2;
        int s = tout + 240; if (s >= OSN) s -= OSN;
        float2 tw   = make_float2((q2 & 1) ? -1.f : 1.f, 0.f);
        float2 step = E[s];
        float2 acc[GL];
#pragma unroll
        for (int l = 0; l < GL; l++) acc[l] = make_float2(0.f, 0.f);
        const float2* sp = S + q2;
#pragma unroll
        for (int m2 = 0; m2 < 20; m2++) {
#pragma unroll
            for (int l = 0; l < GL; l++) {
                float2 a = sp[l * OSN + 20 * m2];
                acc[l].x = fmaf(a.x, tw.x, fmaf(-a.y, tw.y, acc[l].x));
                acc[l].y = fmaf(a.x, tw.y, fmaf( a.y, tw.x, acc[l].y));
            }
            tw = cmul(tw, step);
        }
        float4* Tv = (float4*)(((float2*)g_T1) + ((size_t)b * RESN + tout) * OSN + y0);
        Tv[0] = make_float4(acc[0].x, acc[0].y, acc[1].x, acc[1].y);
        Tv[1] = make_float4(acc[2].x, acc[2].y, acc[3].x, acc[3].y);
        Tv[2] = make_float4(acc[4].x, acc[4].y, acc[5].x, acc[5].y);
        Tv[3] = make_float4(acc[6].x, acc[6].y, acc[7].x, acc[7].y);
    }
}

__global__ void col_dft_kernel(float* __restrict__ out) {
    extern __shared__ float2 shm[];
    float2* xs   = shm;
    float2* S    = shm + GL * OSN;
    float2* E    = shm + 2 * GL * OSN;
    float*  apod = (float*)(shm + 2 * GL * OSN + OSN);

    int t  = threadIdx.x;
    int b  = blockIdx.x / (RESN / GL);
    int x0 = (blockIdx.x % (RESN / GL)) * GL;

    const float2* Tp = ((const float2*)g_T1) + ((size_t)b * RESN + x0) * OSN;
#pragma unroll
    for (int l = 0; l < GL; l++) xs[l * OSN + t] = Tp[(size_t)l * OSN + t];
    {
        float sv, cv;
        sincospif((float)t * (1.0f / 200.0f), &sv, &cv);
        E[t] = make_float2(cv, sv);
    }
    if (t < RESN) apod[t] = apodf(t);
    __syncthreads();

    /* stage 1 */
    {
        int m2 = t / 20, q = t % 20;
        float2 acc[GL];
#pragma unroll
        for (int l = 0; l < GL; l++) acc[l] = make_float2(0.f, 0.f);
        float2 w    = make_float2(1.f, 0.f);
        float2 step = E[20 * q];
        const float2* xp = xs + m2;
#pragma unroll
        for (int m1 = 0; m1 < 20; m1++) {
#pragma unroll
            for (int l = 0; l < GL; l++) {
                float2 a = xp[l * OSN + 20 * m1];
                acc[l].x = fmaf(a.x, w.x, fmaf(-a.y, w.y, acc[l].x));
                acc[l].y = fmaf(a.x, w.y, fmaf( a.y, w.x, acc[l].y));
            }
            w = cmul(w, step);
        }
#pragma unroll
        for (int l = 0; l < GL; l++) S[l * OSN + t] = acc[l];
    }
    __syncthreads();

    /* stage 2 + apodization + final store */
    if (t < RESN) {
        int q2 = t / 16, j = t & 15;
        int tout = 20 * j + q2;
        int s = tout + 240; if (s >= OSN) s -= OSN;
        float2 tw   = make_float2((q2 & 1) ? -1.f : 1.f, 0.f);
        float2 step = E[s];
        float2 acc[GL];
#pragma unroll
        for (int l = 0; l < GL; l++) acc[l] = make_float2(0.f, 0.f);
        const float2* sp = S + q2;
#pragma unroll
        for (int m2 = 0; m2 < 20; m2++) {
#pragma unroll
            for (int l = 0; l < GL; l++) {
                float2 a = sp[l * OSN + 20 * m2];
                acc[l].x = fmaf(a.x, tw.x, fmaf(-a.y, tw.y, acc[l].x));
                acc[l].y = fmaf(a.x, tw.y, fmaf( a.y, tw.x, acc[l].y));
            }
            tw = cmul(tw, step);
        }
        float fy = apod[tout] * (1.0f / 320.0f);
        float fa[GL];
#pragma unroll
        for (int l = 0; l < GL; l++) fa[l] = fy * apod[x0 + l];

        float* po = out + (((size_t)b * 2 * RESN + tout) * RESN + x0);
        float4 r0 = make_float4(acc[0].x * fa[0], acc[1].x * fa[1],
                                acc[2].x * fa[2], acc[3].x * fa[3]);
        float4 r1 = make_float4(acc[4].x * fa[4], acc[5].x * fa[5],
                                acc[6].x * fa[6], acc[7].x * fa[7]);
        ((float4*)po)[0] = r0;
        ((float4*)po)[1] = r1;

        float* pi = po + RESN * RESN;   /* channel 1 = imag */
        float4 i0v = make_float4(acc[0].y * fa[0], acc[1].y * fa[1],
                                 acc[2].y * fa[2], acc[3].y * fa[3]);
        float4 i1v = make_float4(acc[4].y * fa[4], acc[5].y * fa[5],
                                 acc[6].y * fa[6], acc[7].y * fa[7]);
        ((float4*)pi)[0] = i0v;
        ((float4*)pi)[1] = i1v;
    }
}

extern "C" void kernel_launch(void* const* d_in, const int* in_sizes, int n_in,
                              void* d_out, int out_size) {
    const float* ksp  = (const float*)d_in[0];
    const float* traj = (const float*)d_in[1];
    float* out = (float*)d_out;

    const int SMEM_ROW = (2 * GL * OSN + OSN) * (int)sizeof(float2);          /* 54400 B */
    const int SMEM_COL = SMEM_ROW + RESN * (int)sizeof(float);                /* 55680 B */

    cudaFuncSetAttribute(row_dft_kernel, cudaFuncAttributeMaxDynamicSharedMemorySize, SMEM_ROW);
    cudaFuncSetAttribute(col_dft_kernel, cudaFuncAttributeMaxDynamicSharedMemorySize, SMEM_COL);

    zero_grid_kernel<<<(NB * OSN * OSN * 2 / 4 + 255) / 256, 256>>>();
    grid_scatter_kernel<<<(NB * MTRAJ + 255) / 256, 256>>>(ksp, traj);
    row_dft_kernel<<<NB * (OSN / GL), OSN, SMEM_ROW>>>();
    col_dft_kernel<<<NB * (RESN / GL), OSN, SMEM_COL>>>(out);
}

// round 4
// speedup vs baseline: 2.0599x; 1.2090x over previous
#include <cuda_runtime.h>
#include <math.h>

#define RESN   320
#define MTRAJ  25600
#define NB     16
#define OSN    400
#define GL     8

#define BETA_F  6.99665877f      /* pi*sqrt(4.96) */
#define BETA2_F 48.9532378f      /* pi^2*4.96 */

typedef unsigned long long u64;

/* scratch: gridded k-space (complex) and row-pass intermediate (complex, transposed) */
__device__ __align__(16) float g_grid[NB * OSN * OSN * 2];
__device__ __align__(16) float g_T1[NB * RESN * OSN * 2];

/* ---------------- packed f32x2 helpers ---------------- */
__device__ __forceinline__ u64 dup2(float x) {
    u64 r; asm("mov.b64 %0, {%1, %1};" : "=l"(r) : "f"(x)); return r;
}
__device__ __forceinline__ void unpack2(u64 p, float& lo, float& hi) {
    asm("mov.b64 {%0, %1}, %2;" : "=f"(lo), "=f"(hi) : "l"(p));
}
__device__ __forceinline__ u64 fma2(u64 a, u64 b, u64 c) {
    u64 d; asm("fma.rn.f32x2 %0, %1, %2, %3;" : "=l"(d) : "l"(a), "l"(b), "l"(c)); return d;
}

__device__ __forceinline__ void red_add_v2(float* p, float a, float b) {
    asm volatile("red.global.add.v2.f32 [%0], {%1, %2};"
                 :: "l"(p), "f"(a), "f"(b) : "memory");
}
__device__ __forceinline__ void red_add_v4(float* p, float a, float b, float c, float d) {
    asm volatile("red.global.add.v4.f32 [%0], {%1, %2, %3, %4};"
                 :: "l"(p), "f"(a), "f"(b), "f"(c), "f"(d) : "memory");
}

/* ---------------- Bessel I0 (A&S 9.8.1 / 9.8.2) ---------------- */
__device__ __forceinline__ float i0f_dev(float x) {
    if (x < 3.75f) {
        float t = x * (1.0f / 3.75f);
        t *= t;
        return 1.0f + t * (3.5156229f + t * (3.0899424f + t * (1.2067492f
             + t * (0.2659732f + t * (0.0360768f + t * 0.0045813f)))));
    } else {
        float t = 3.75f / x;
        float p = 0.39894228f + t * (0.01328592f + t * (0.00225319f + t * (-0.00157565f
                + t * (0.00916281f + t * (-0.02057706f + t * (0.02635537f
                + t * (-0.01647633f + t * 0.00392377f)))))));
        return expf(x) * rsqrtf(x) * p;
    }
}

__device__ __forceinline__ float kbw(float delta) {
    float u  = delta * 0.5f;
    float tt = fmaxf(1.0f - u * u, 0.0f);
    return i0f_dev(BETA_F * sqrtf(tt)) * 0.25f;
}

__device__ __forceinline__ float apodf(int i) {
    float d = (float)(i - 160) * 0.0314159265f;
    float a = sqrtf(fmaxf(BETA2_F - d * d, 1e-12f));
    return a / sinhf(a);
}

__device__ __forceinline__ float2 cmul(float2 a, float2 b) {
    return make_float2(fmaf(a.x, b.x, -a.y * b.y), fmaf(a.x, b.y, a.y * b.x));
}

/* ---------------- kernel 1: zero the scatter grid ---------------- */
__global__ void zero_grid_kernel() {
    int i = blockIdx.x * blockDim.x + threadIdx.x;
    if (i < NB * OSN * OSN * 2 / 4)
        ((float4*)g_grid)[i] = make_float4(0.f, 0.f, 0.f, 0.f);
}

/* ------- kernel 2: bilinear sample + Kaiser-Bessel scatter ------- */
__global__ void grid_scatter_kernel(const float* __restrict__ ksp,
                                    const float* __restrict__ traj) {
    int idx = blockIdx.x * blockDim.x + threadIdx.x;
    if (idx >= NB * MTRAJ) return;
    int b = idx & (NB - 1);
    int m = idx >> 4;

    float t0 = traj[2 * m + 0];
    float t1 = traj[2 * m + 1];

    /* bilinear sample of (2-ch) k-space image: t0 -> x, t1 -> y */
    float px = (t0 * (1.0f / 160.0f) + 1.0f) * 0.5f * 319.0f;
    float py = (t1 * (1.0f / 160.0f) + 1.0f) * 0.5f * 319.0f;
    float x0f = floorf(px), y0f = floorf(py);
    float wx1 = px - x0f,   wy1 = py - y0f;
    int   x0  = (int)x0f,   y0  = (int)y0f;

    const float* img = ksp + (size_t)b * (RESN * RESN * 2);
    float yr = 0.f, yi = 0.f;
#pragma unroll
    for (int dy = 0; dy < 2; dy++) {
#pragma unroll
        for (int dx = 0; dx < 2; dx++) {
            int  xi  = x0 + dx, yv = y0 + dy;
            float w  = (dx ? wx1 : 1.0f - wx1) * (dy ? wy1 : 1.0f - wy1);
            bool inb = (xi >= 0) && (xi < RESN) && (yv >= 0) && (yv < RESN);
            int  xc  = min(max(xi, 0), RESN - 1);
            int  yc  = min(max(yv, 0), RESN - 1);
            float2 v = *(const float2*)(img + ((size_t)yc * RESN + xc) * 2);
            float wm = inb ? w : 0.0f;
            yr += v.x * wm;
            yi += v.y * wm;
        }
    }

    /* KB gridding: coord column 0 -> grid ROW (y), column 1 -> grid COL (x) */
    float cy = t0 * 1.25f + 200.0f;
    float cx = t1 * 1.25f + 200.0f;
    int sy = (int)ceilf(cy - 2.0f);
    int sx = (int)ceilf(cx - 2.0f);

    float wy[4], wx[4];
    int   iy[4];
#pragma unroll
    for (int j = 0; j < 4; j++) {
        wy[j] = kbw(cy - (float)(sy + j));
        wx[j] = kbw(cx - (float)(sx + j));
        int a = sy + j; if (a < 0) a += OSN; if (a >= OSN) a -= OSN; iy[j] = a;
    }
    float pxr[4], pxi[4];
#pragma unroll
    for (int j = 0; j < 4; j++) { pxr[j] = wx[j] * yr; pxi[j] = wx[j] * yi; }

    float* gb = g_grid + (size_t)b * (OSN * OSN * 2);

    if (sx >= 0 && sx <= OSN - 4) {
        if ((sx & 1) == 0) {
#pragma unroll
            for (int jy = 0; jy < 4; jy++) {
                float wv = wy[jy];
                float* base = gb + ((size_t)iy[jy] * OSN + sx) * 2;
                red_add_v4(base,     wv * pxr[0], wv * pxi[0], wv * pxr[1], wv * pxi[1]);
                red_add_v4(base + 4, wv * pxr[2], wv * pxi[2], wv * pxr[3], wv * pxi[3]);
            }
        } else {
#pragma unroll
            for (int jy = 0; jy < 4; jy++) {
                float wv = wy[jy];
                float* base = gb + ((size_t)iy[jy] * OSN + sx) * 2;
                red_add_v2(base,     wv * pxr[0], wv * pxi[0]);
                red_add_v4(base + 2, wv * pxr[1], wv * pxi[1], wv * pxr[2], wv * pxi[2]);
                red_add_v2(base + 6, wv * pxr[3], wv * pxi[3]);
            }
        }
    } else {
        int ix[4];
#pragma unroll
        for (int j = 0; j < 4; j++) {
            int c = sx + j; if (c < 0) c += OSN; if (c >= OSN) c -= OSN; ix[j] = c;
        }
#pragma unroll
        for (int jy = 0; jy < 4; jy++) {
#pragma unroll
            for (int jx = 0; jx < 4; jx++) {
                float w = wy[jy] * wx[jx];
                float* cell = gb + ((size_t)iy[jy] * OSN + ix[jx]) * 2;
                red_add_v2(cell, yr * w, yi * w);
            }
        }
    }
}

/* --------------- centered 400-pt DFT, Cooley-Tukey 20x20 ---------------
   out[t] = sum_m x[m] * E[(m-200)(t-160) mod 400],  E[p] = exp(+2i*pi*p/400)
   Planar smem layout, l-contiguous with pad 10 (8B-aligned pairs):
     xs_x[m*10 + l], xs_y[m*10 + l]; S likewise.
   Inner complex MAC done on l-pairs via packed fma.rn.f32x2.
------------------------------------------------------------------------ */

#define LSTR 10

__global__ void row_dft_kernel() {
    extern __shared__ float sh[];
    float*  xs_x = sh;
    float*  xs_y = sh + OSN * LSTR;
    float*  S_x  = sh + 2 * OSN * LSTR;
    float*  S_y  = sh + 3 * OSN * LSTR;
    float2* E    = (float2*)(sh + 4 * OSN * LSTR);

    int t  = threadIdx.x;                       /* 0..399 */
    int b  = blockIdx.x / (OSN / GL);
    int y0 = (blockIdx.x % (OSN / GL)) * GL;

    const float2* gp = ((const float2*)g_grid) + ((size_t)b * OSN + y0) * OSN;
#pragma unroll
    for (int l = 0; l < GL; l++) {
        float2 v = gp[(size_t)l * OSN + t];
        xs_x[t * LSTR + l] = v.x;
        xs_y[t * LSTR + l] = v.y;
    }
    {
        float sv, cv;
        sincospif((float)t * (1.0f / 200.0f), &sv, &cv);
        E[t] = make_float2(cv, sv);
    }
    __syncthreads();

    /* stage 1: thread (m2 = t/20, q = t%20) -> S row m2*20+q */
    {
        int m2 = t / 20, q = t % 20;
        u64 accX[4] = {0,0,0,0}, accY[4] = {0,0,0,0};
        float2 w    = make_float2(1.f, 0.f);
        float2 step = E[20 * q];
        const float* bx = xs_x + m2 * LSTR;
        const float* by = xs_y + m2 * LSTR;
#pragma unroll
        for (int m1 = 0; m1 < 20; m1++) {
            u64 wxp  = dup2(w.x);
            u64 wyp  = dup2(w.y);
            u64 nwyp = dup2(-w.y);
#pragma unroll
            for (int p = 0; p < 4; p++) {
                u64 aX = *(const u64*)(bx + m1 * (20 * LSTR) + 2 * p);
                u64 aY = *(const u64*)(by + m1 * (20 * LSTR) + 2 * p);
                accX[p] = fma2(aY, nwyp, fma2(aX, wxp, accX[p]));
                accY[p] = fma2(aY, wxp,  fma2(aX, wyp, accY[p]));
            }
            w = cmul(w, step);
        }
        int srow = (m2 * 20 + q) * LSTR;
#pragma unroll
        for (int p = 0; p < 4; p++) {
            *(u64*)(S_x + srow + 2 * p) = accX[p];
            *(u64*)(S_y + srow + 2 * p) = accY[p];
        }
    }
    __syncthreads();

    /* stage 2: thread (q2 = t/16, j = t%16) -> out column tout = 20*j + q2 */
    if (t < RESN) {
        int q2 = t / 16, j = t & 15;
        int tout = 20 * j + q2;
        int s = tout + 240; if (s >= OSN) s -= OSN;
        float2 tw   = make_float2((q2 & 1) ? -1.f : 1.f, 0.f);
        float2 step = E[s];
        u64 accX[4] = {0,0,0,0}, accY[4] = {0,0,0,0};
        const float* bx = S_x + q2 * LSTR;
        const float* by = S_y + q2 * LSTR;
#pragma unroll
        for (int m2 = 0; m2 < 20; m2++) {
            u64 wxp  = dup2(tw.x);
            u64 wyp  = dup2(tw.y);
            u64 nwyp = dup2(-tw.y);
#pragma unroll
            for (int p = 0; p < 4; p++) {
                u64 aX = *(const u64*)(bx + m2 * (20 * LSTR) + 2 * p);
                u64 aY = *(const u64*)(by + m2 * (20 * LSTR) + 2 * p);
                accX[p] = fma2(aY, nwyp, fma2(aX, wxp, accX[p]));
                accY[p] = fma2(aY, wxp,  fma2(aX, wyp, accY[p]));
            }
            tw = cmul(tw, step);
        }
        float4* Tv = (float4*)(((float2*)g_T1) + ((size_t)b * RESN + tout) * OSN + y0);
#pragma unroll
        for (int p = 0; p < 4; p++) {
            float xr0, xr1, xi0, xi1;
            unpack2(accX[p], xr0, xr1);
            unpack2(accY[p], xi0, xi1);
            Tv[p] = make_float4(xr0, xi0, xr1, xi1);
        }
    }
}

__global__ void col_dft_kernel(float* __restrict__ out) {
    extern __shared__ float sh[];
    float*  xs_x = sh;
    float*  xs_y = sh + OSN * LSTR;
    float*  S_x  = sh + 2 * OSN * LSTR;
    float*  S_y  = sh + 3 * OSN * LSTR;
    float2* E    = (float2*)(sh + 4 * OSN * LSTR);
    float*  apod = sh + 4 * OSN * LSTR + 2 * OSN;

    int t  = threadIdx.x;
    int b  = blockIdx.x / (RESN / GL);
    int x0 = (blockIdx.x % (RESN / GL)) * GL;

    const float2* Tp = ((const float2*)g_T1) + ((size_t)b * RESN + x0) * OSN;
#pragma unroll
    for (int l = 0; l < GL; l++) {
        float2 v = Tp[(size_t)l * OSN + t];
        xs_x[t * LSTR + l] = v.x;
        xs_y[t * LSTR + l] = v.y;
    }
    {
        float sv, cv;
        sincospif((float)t * (1.0f / 200.0f), &sv, &cv);
        E[t] = make_float2(cv, sv);
    }
    if (t < RESN) apod[t] = apodf(t);
    __syncthreads();

    /* stage 1 */
    {
        int m2 = t / 20, q = t % 20;
        u64 accX[4] = {0,0,0,0}, accY[4] = {0,0,0,0};
        float2 w    = make_float2(1.f, 0.f);
        float2 step = E[20 * q];
        const float* bx = xs_x + m2 * LSTR;
        const float* by = xs_y + m2 * LSTR;
#pragma unroll
        for (int m1 = 0; m1 < 20; m1++) {
            u64 wxp  = dup2(w.x);
            u64 wyp  = dup2(w.y);
            u64 nwyp = dup2(-w.y);
#pragma unroll
            for (int p = 0; p < 4; p++) {
                u64 aX = *(const u64*)(bx + m1 * (20 * LSTR) + 2 * p);
                u64 aY = *(const u64*)(by + m1 * (20 * LSTR) + 2 * p);
                accX[p] = fma2(aY, nwyp, fma2(aX, wxp, accX[p]));
                accY[p] = fma2(aY, wxp,  fma2(aX, wyp, accY[p]));
            }
            w = cmul(w, step);
        }
        int srow = (m2 * 20 + q) * LSTR;
#pragma unroll
        for (int p = 0; p < 4; p++) {
            *(u64*)(S_x + srow + 2 * p) = accX[p];
            *(u64*)(S_y + srow + 2 * p) = accY[p];
        }
    }
    __syncthreads();

    /* stage 2 + apodization + final store */
    if (t < RESN) {
        int q2 = t / 16, j = t & 15;
        int tout = 20 * j + q2;
        int s = tout + 240; if (s >= OSN) s -= OSN;
        float2 tw   = make_float2((q2 & 1) ? -1.f : 1.f, 0.f);
        float2 step = E[s];
        u64 accX[4] = {0,0,0,0}, accY[4] = {0,0,0,0};
        const float* bx = S_x + q2 * LSTR;
        const float* by = S_y + q2 * LSTR;
#pragma unroll
        for (int m2 = 0; m2 < 20; m2++) {
            u64 wxp  = dup2(tw.x);
            u64 wyp  = dup2(tw.y);
            u64 nwyp = dup2(-tw.y);
#pragma unroll
            for (int p = 0; p < 4; p++) {
                u64 aX = *(const u64*)(bx + m2 * (20 * LSTR) + 2 * p);
                u64 aY = *(const u64*)(by + m2 * (20 * LSTR) + 2 * p);
                accX[p] = fma2(aY, nwyp, fma2(aX, wxp, accX[p]));
                accY[p] = fma2(aY, wxp,  fma2(aX, wyp, accY[p]));
            }
            tw = cmul(tw, step);
        }
        float fy = apod[tout] * (1.0f / 320.0f);
        float fa[GL];
#pragma unroll
        for (int l = 0; l < GL; l++) fa[l] = fy * apod[x0 + l];

        float xr[GL], xi[GL];
#pragma unroll
        for (int p = 0; p < 4; p++) {
            unpack2(accX[p], xr[2 * p], xr[2 * p + 1]);
            unpack2(accY[p], xi[2 * p], xi[2 * p + 1]);
        }

        float* po = out + (((size_t)b * 2 * RESN + tout) * RESN + x0);
        ((float4*)po)[0] = make_float4(xr[0] * fa[0], xr[1] * fa[1], xr[2] * fa[2], xr[3] * fa[3]);
        ((float4*)po)[1] = make_float4(xr[4] * fa[4], xr[5] * fa[5], xr[6] * fa[6], xr[7] * fa[7]);

        float* pi = po + RESN * RESN;   /* channel 1 = imag */
        ((float4*)pi)[0] = make_float4(xi[0] * fa[0], xi[1] * fa[1], xi[2] * fa[2], xi[3] * fa[3]);
        ((float4*)pi)[1] = make_float4(xi[4] * fa[4], xi[5] * fa[5], xi[6] * fa[6], xi[7] * fa[7]);
    }
}

extern "C" void kernel_launch(void* const* d_in, const int* in_sizes, int n_in,
                              void* d_out, int out_size) {
    const float* ksp  = (const float*)d_in[0];
    const float* traj = (const float*)d_in[1];
    float* out = (float*)d_out;

    const int SMEM_ROW = (4 * OSN * LSTR + 2 * OSN) * (int)sizeof(float);          /* 67200 B */
    const int SMEM_COL = SMEM_ROW + RESN * (int)sizeof(float);                     /* 68480 B */

    cudaFuncSetAttribute(row_dft_kernel, cudaFuncAttributeMaxDynamicSharedMemorySize, SMEM_ROW);
    cudaFuncSetAttribute(col_dft_kernel, cudaFuncAttributeMaxDynamicSharedMemorySize, SMEM_COL);

    zero_grid_kernel<<<(NB * OSN * OSN * 2 / 4 + 255) / 256, 256>>>();
    grid_scatter_kernel<<<(NB * MTRAJ + 255) / 256, 256>>>(ksp, traj);
    row_dft_kernel<<<NB * (OSN / GL), OSN, SMEM_ROW>>>();
    col_dft_kernel<<<NB * (RESN / GL), OSN, SMEM_COL>>>(out);
}

// round 5
// speedup vs baseline: 2.1141x; 1.0263x over previous
#include <cuda_runtime.h>
#include <math.h>

#define RESN   320
#define MTRAJ  25600
#define NB     16
#define OSN    400
#define GL     8
#define LSTR   12   /* l-stride in floats: 48B, keeps every row 16B-aligned */

#define BETA_F  6.99665877f      /* pi*sqrt(4.96) */
#define BETA2_F 48.9532378f      /* pi^2*4.96 */

typedef unsigned long long u64;

/* scratch: gridded k-space (complex) and row-pass intermediate (complex, transposed) */
__device__ __align__(16) float g_grid[NB * OSN * OSN * 2];
__device__ __align__(16) float g_T1[NB * RESN * OSN * 2];

/* ---------------- packed f32x2 helpers ---------------- */
__device__ __forceinline__ u64 dup2(float x) {
    u64 r; asm("mov.b64 %0, {%1, %1};" : "=l"(r) : "f"(x)); return r;
}
__device__ __forceinline__ void unpack2(u64 p, float& lo, float& hi) {
    asm("mov.b64 {%0, %1}, %2;" : "=f"(lo), "=f"(hi) : "l"(p));
}
__device__ __forceinline__ u64 fma2(u64 a, u64 b, u64 c) {
    u64 d; asm("fma.rn.f32x2 %0, %1, %2, %3;" : "=l"(d) : "l"(a), "l"(b), "l"(c)); return d;
}

__device__ __forceinline__ void red_add_v2(float* p, float a, float b) {
    asm volatile("red.global.add.v2.f32 [%0], {%1, %2};"
                 :: "l"(p), "f"(a), "f"(b) : "memory");
}
__device__ __forceinline__ void red_add_v4(float* p, float a, float b, float c, float d) {
    asm volatile("red.global.add.v4.f32 [%0], {%1, %2, %3, %4};"
                 :: "l"(p), "f"(a), "f"(b), "f"(c), "f"(d) : "memory");
}

/* ---------------- Bessel I0 (A&S 9.8.1 / 9.8.2) ---------------- */
__device__ __forceinline__ float i0f_dev(float x) {
    if (x < 3.75f) {
        float t = x * (1.0f / 3.75f);
        t *= t;
        return 1.0f + t * (3.5156229f + t * (3.0899424f + t * (1.2067492f
             + t * (0.2659732f + t * (0.0360768f + t * 0.0045813f)))));
    } else {
        float t = 3.75f / x;
        float p = 0.39894228f + t * (0.01328592f + t * (0.00225319f + t * (-0.00157565f
                + t * (0.00916281f + t * (-0.02057706f + t * (0.02635537f
                + t * (-0.01647633f + t * 0.00392377f)))))));
        return expf(x) * rsqrtf(x) * p;
    }
}

__device__ __forceinline__ float kbw(float delta) {
    float u  = delta * 0.5f;
    float tt = fmaxf(1.0f - u * u, 0.0f);
    return i0f_dev(BETA_F * sqrtf(tt)) * 0.25f;
}

__device__ __forceinline__ float apodf(int i) {
    float d = (float)(i - 160) * 0.0314159265f;
    float a = sqrtf(fmaxf(BETA2_F - d * d, 1e-12f));
    return a / sinhf(a);
}

__device__ __forceinline__ float2 cmul(float2 a, float2 b) {
    return make_float2(fmaf(a.x, b.x, -a.y * b.y), fmaf(a.x, b.y, a.y * b.x));
}

/* ---------------- kernel 1: zero the scatter grid ---------------- */
__global__ void zero_grid_kernel() {
    int i = blockIdx.x * blockDim.x + threadIdx.x;
    if (i < NB * OSN * OSN * 2 / 4)
        ((float4*)g_grid)[i] = make_float4(0.f, 0.f, 0.f, 0.f);
}

/* ------- kernel 2: bilinear sample + Kaiser-Bessel scatter ------- */
__global__ void grid_scatter_kernel(const float* __restrict__ ksp,
                                    const float* __restrict__ traj) {
    int idx = blockIdx.x * blockDim.x + threadIdx.x;
    if (idx >= NB * MTRAJ) return;
    int b = idx & (NB - 1);
    int m = idx >> 4;

    float t0 = traj[2 * m + 0];
    float t1 = traj[2 * m + 1];

    /* bilinear sample of (2-ch) k-space image: t0 -> x, t1 -> y */
    float px = (t0 * (1.0f / 160.0f) + 1.0f) * 0.5f * 319.0f;
    float py = (t1 * (1.0f / 160.0f) + 1.0f) * 0.5f * 319.0f;
    float x0f = floorf(px), y0f = floorf(py);
    float wx1 = px - x0f,   wy1 = py - y0f;
    int   x0  = (int)x0f,   y0  = (int)y0f;

    const float* img = ksp + (size_t)b * (RESN * RESN * 2);
    float yr = 0.f, yi = 0.f;
#pragma unroll
    for (int dy = 0; dy < 2; dy++) {
#pragma unroll
        for (int dx = 0; dx < 2; dx++) {
            int  xi  = x0 + dx, yv = y0 + dy;
            float w  = (dx ? wx1 : 1.0f - wx1) * (dy ? wy1 : 1.0f - wy1);
            bool inb = (xi >= 0) && (xi < RESN) && (yv >= 0) && (yv < RESN);
            int  xc  = min(max(xi, 0), RESN - 1);
            int  yc  = min(max(yv, 0), RESN - 1);
            float2 v = *(const float2*)(img + ((size_t)yc * RESN + xc) * 2);
            float wm = inb ? w : 0.0f;
            yr += v.x * wm;
            yi += v.y * wm;
        }
    }

    /* KB gridding: coord column 0 -> grid ROW (y), column 1 -> grid COL (x) */
    float cy = t0 * 1.25f + 200.0f;
    float cx = t1 * 1.25f + 200.0f;
    int sy = (int)ceilf(cy - 2.0f);
    int sx = (int)ceilf(cx - 2.0f);

    float wy[4], wx[4];
    int   iy[4];
#pragma unroll
    for (int j = 0; j < 4; j++) {
        wy[j] = kbw(cy - (float)(sy + j));
        wx[j] = kbw(cx - (float)(sx + j));
        int a = sy + j; if (a < 0) a += OSN; if (a >= OSN) a -= OSN; iy[j] = a;
    }
    float pxr[4], pxi[4];
#pragma unroll
    for (int j = 0; j < 4; j++) { pxr[j] = wx[j] * yr; pxi[j] = wx[j] * yi; }

    float* gb = g_grid + (size_t)b * (OSN * OSN * 2);

    if (sx >= 0 && sx <= OSN - 4) {
        if ((sx & 1) == 0) {
#pragma unroll
            for (int jy = 0; jy < 4; jy++) {
                float wv = wy[jy];
                float* base = gb + ((size_t)iy[jy] * OSN + sx) * 2;
                red_add_v4(base,     wv * pxr[0], wv * pxi[0], wv * pxr[1], wv * pxi[1]);
                red_add_v4(base + 4, wv * pxr[2], wv * pxi[2], wv * pxr[3], wv * pxi[3]);
            }
        } else {
#pragma unroll
            for (int jy = 0; jy < 4; jy++) {
                float wv = wy[jy];
                float* base = gb + ((size_t)iy[jy] * OSN + sx) * 2;
                red_add_v2(base,     wv * pxr[0], wv * pxi[0]);
                red_add_v4(base + 2, wv * pxr[1], wv * pxi[1], wv * pxr[2], wv * pxi[2]);
                red_add_v2(base + 6, wv * pxr[3], wv * pxi[3]);
            }
        }
    } else {
        int ix[4];
#pragma unroll
        for (int j = 0; j < 4; j++) {
            int c = sx + j; if (c < 0) c += OSN; if (c >= OSN) c -= OSN; ix[j] = c;
        }
#pragma unroll
        for (int jy = 0; jy < 4; jy++) {
#pragma unroll
            for (int jx = 0; jx < 4; jx++) {
                float w = wy[jy] * wx[jx];
                float* cell = gb + ((size_t)iy[jy] * OSN + ix[jx]) * 2;
                red_add_v2(cell, yr * w, yi * w);
            }
        }
    }
}

/* --------------- centered 400-pt DFT, Cooley-Tukey 20x20 ---------------
   out[t] = sum_m x[m] * E[(m-200)(t-160) mod 400],  E[p] = exp(+2i*pi*p/400)
   Planar smem layout, l-contiguous with pad LSTR=12 (16B-aligned rows):
     xs_x[m*12 + l], xs_y[m*12 + l].
   Stage-1 output S is written back IN PLACE over xs (extra barrier) so data
   smem is 2 arrays, not 4 -> 5 CTAs/SM.
   Inner complex MAC: packed fma.rn.f32x2 fed by 16B LDS (ulonglong2).
------------------------------------------------------------------------ */

struct DftAcc { u64 X[4]; u64 Y[4]; };

__device__ __forceinline__ void dft_mac20(DftAcc& A, const float* bx, const float* by,
                                          int stride_f, float2 w0, float2 step) {
    float2 w = w0;
#pragma unroll
    for (int mm = 0; mm < 20; mm++) {
        u64 wxp  = dup2(w.x);
        u64 wyp  = dup2(w.y);
        u64 nwyp = dup2(-w.y);
        const float* px = bx + mm * stride_f;
        const float* py = by + mm * stride_f;
#pragma unroll
        for (int h = 0; h < 2; h++) {
            ulonglong2 aX = *(const ulonglong2*)(px + 4 * h);
            ulonglong2 aY = *(const ulonglong2*)(py + 4 * h);
            A.X[2*h]   = fma2(aY.x, nwyp, fma2(aX.x, wxp, A.X[2*h]));
            A.Y[2*h]   = fma2(aY.x, wyp == 0 ? wyp : wyp, A.Y[2*h]);   /* placeholder overwritten below */
            A.Y[2*h]   = fma2(aY.x, wxp,  fma2(aX.x, wyp, A.Y[2*h]));
            A.X[2*h+1] = fma2(aY.y, nwyp, fma2(aX.y, wxp, A.X[2*h+1]));
            A.Y[2*h+1] = fma2(aY.y, wxp,  fma2(aX.y, wyp, A.Y[2*h+1]));
        }
        w = cmul(w, step);
    }
}

/* NOTE: the placeholder line above would corrupt results; use explicit body instead. */

#define DFT_MAC20(A, bx, by, stride_f, w0, step)                                 \
    {                                                                            \
        float2 w = (w0);                                                         \
        _Pragma("unroll")                                                        \
        for (int mm = 0; mm < 20; mm++) {                                        \
            u64 wxp  = dup2(w.x);                                                \
            u64 wyp  = dup2(w.y);                                                \
            u64 nwyp = dup2(-w.y);                                               \
            const float* px_ = (bx) + mm * (stride_f);                           \
            const float* py_ = (by) + mm * (stride_f);                           \
            ulonglong2 aX0 = *(const ulonglong2*)(px_);                          \
            ulonglong2 aY0 = *(const ulonglong2*)(py_);                          \
            ulonglong2 aX1 = *(const ulonglong2*)(px_ + 4);                      \
            ulonglong2 aY1 = *(const ulonglong2*)(py_ + 4);                      \
            A.X[0] = fma2(aY0.x, nwyp, fma2(aX0.x, wxp, A.X[0]));                \
            A.Y[0] = fma2(aY0.x, wxp,  fma2(aX0.x, wyp, A.Y[0]));                \
            A.X[1] = fma2(aY0.y, nwyp, fma2(aX0.y, wxp, A.X[1]));                \
            A.Y[1] = fma2(aY0.y, wxp,  fma2(aX0.y, wyp, A.Y[1]));                \
            A.X[2] = fma2(aY1.x, nwyp, fma2(aX1.x, wxp, A.X[2]));                \
            A.Y[2] = fma2(aY1.x, wxp,  fma2(aX1.x, wyp, A.Y[2]));                \
            A.X[3] = fma2(aY1.y, nwyp, fma2(aX1.y, wxp, A.X[3]));                \
            A.Y[3] = fma2(aY1.y, wxp,  fma2(aX1.y, wyp, A.Y[3]));                \
            w = cmul(w, step);                                                   \
        }                                                                        \
    }

__global__ void row_dft_kernel() {
    extern __shared__ float sh[];
    float*  xs_x = sh;
    float*  xs_y = sh + OSN * LSTR;
    float2* E    = (float2*)(sh + 2 * OSN * LSTR);

    int t  = threadIdx.x;                       /* 0..399 */
    int b  = blockIdx.x / (OSN / GL);
    int y0 = (blockIdx.x % (OSN / GL)) * GL;

    const float2* gp = ((const float2*)g_grid) + ((size_t)b * OSN + y0) * OSN;
#pragma unroll
    for (int l = 0; l < GL; l++) {
        float2 v = gp[(size_t)l * OSN + t];
        xs_x[t * LSTR + l] = v.x;
        xs_y[t * LSTR + l] = v.y;
    }
    {
        float sv, cv;
        sincospif((float)t * (1.0f / 200.0f), &sv, &cv);
        E[t] = make_float2(cv, sv);
    }
    __syncthreads();

    /* stage 1: thread (m2 = t/20, q = t%20) -> S row m2*20+q (in place) */
    int m2 = t / 20, q = t % 20;
    DftAcc A; 
#pragma unroll
    for (int p = 0; p < 4; p++) { A.X[p] = 0; A.Y[p] = 0; }
    {
        float2 step = E[20 * q];
        DFT_MAC20(A, xs_x + m2 * LSTR, xs_y + m2 * LSTR, 20 * LSTR,
                  make_float2(1.f, 0.f), step);
    }
    __syncthreads();
    {
        int srow = (m2 * 20 + q) * LSTR;
#pragma unroll
        for (int p = 0; p < 4; p++) {
            *(u64*)(xs_x + srow + 2 * p) = A.X[p];
            *(u64*)(xs_y + srow + 2 * p) = A.Y[p];
        }
    }
    __syncthreads();

    /* stage 2: thread (q2 = t/16, j = t%16) -> out column tout = 20*j + q2 */
    if (t < RESN) {
        int q2 = t / 16, j = t & 15;
        int tout = 20 * j + q2;
        int s = tout + 240; if (s >= OSN) s -= OSN;
        DftAcc B;
#pragma unroll
        for (int p = 0; p < 4; p++) { B.X[p] = 0; B.Y[p] = 0; }
        DFT_MAC20(B, xs_x + q2 * LSTR, xs_y + q2 * LSTR, 20 * LSTR,
                  make_float2((q2 & 1) ? -1.f : 1.f, 0.f), E[s]);

        float4* Tv = (float4*)(((float2*)g_T1) + ((size_t)b * RESN + tout) * OSN + y0);
#pragma unroll
        for (int p = 0; p < 4; p++) {
            float xr0, xr1, xi0, xi1;
            unpack2(B.X[p], xr0, xr1);
            unpack2(B.Y[p], xi0, xi1);
            Tv[p] = make_float4(xr0, xi0, xr1, xi1);
        }
    }
}

__global__ void col_dft_kernel(float* __restrict__ out) {
    extern __shared__ float sh[];
    float*  xs_x = sh;
    float*  xs_y = sh + OSN * LSTR;
    float2* E    = (float2*)(sh + 2 * OSN * LSTR);
    float*  apod = sh + 2 * OSN * LSTR + 2 * OSN;

    int t  = threadIdx.x;
    int b  = blockIdx.x / (RESN / GL);
    int x0 = (blockIdx.x % (RESN / GL)) * GL;

    const float2* Tp = ((const float2*)g_T1) + ((size_t)b * RESN + x0) * OSN;
#pragma unroll
    for (int l = 0; l < GL; l++) {
        float2 v = Tp[(size_t)l * OSN + t];
        xs_x[t * LSTR + l] = v.x;
        xs_y[t * LSTR + l] = v.y;
    }
    {
        float sv, cv;
        sincospif((float)t * (1.0f / 200.0f), &sv, &cv);
        E[t] = make_float2(cv, sv);
    }
    if (t < RESN) apod[t] = apodf(t);
    __syncthreads();

    /* stage 1 (in place) */
    int m2 = t / 20, q = t % 20;
    DftAcc A;
#pragma unroll
    for (int p = 0; p < 4; p++) { A.X[p] = 0; A.Y[p] = 0; }
    {
        float2 step = E[20 * q];
        DFT_MAC20(A, xs_x + m2 * LSTR, xs_y + m2 * LSTR, 20 * LSTR,
                  make_float2(1.f, 0.f), step);
    }
    __syncthreads();
    {
        int srow = (m2 * 20 + q) * LSTR;
#pragma unroll
        for (int p = 0; p < 4; p++) {
            *(u64*)(xs_x + srow + 2 * p) = A.X[p];
            *(u64*)(xs_y + srow + 2 * p) = A.Y[p];
        }
    }
    __syncthreads();

    /* stage 2 + apodization + final store */
    if (t < RESN) {
        int q2 = t / 16, j = t & 15;
        int tout = 20 * j + q2;
        int s = tout + 240; if (s >= OSN) s -= OSN;
        DftAcc B;
#pragma unroll
        for (int p = 0; p < 4; p++) { B.X[p] = 0; B.Y[p] = 0; }
        DFT_MAC20(B, xs_x + q2 * LSTR, xs_y + q2 * LSTR, 20 * LSTR,
                  make_float2((q2 & 1) ? -1.f : 1.f, 0.f), E[s]);

        float fy = apod[tout] * (1.0f / 320.0f);
        float fa[GL];
#pragma unroll
        for (int l = 0; l < GL; l++) fa[l] = fy * apod[x0 + l];

        float xr[GL], xi[GL];
#pragma unroll
        for (int p = 0; p < 4; p++) {
            unpack2(B.X[p], xr[2 * p], xr[2 * p + 1]);
            unpack2(B.Y[p], xi[2 * p], xi[2 * p + 1]);
        }

        float* po = out + (((size_t)b * 2 * RESN + tout) * RESN + x0);
        ((float4*)po)[0] = make_float4(xr[0] * fa[0], xr[1] * fa[1], xr[2] * fa[2], xr[3] * fa[3]);
        ((float4*)po)[1] = make_float4(xr[4] * fa[4], xr[5] * fa[5], xr[6] * fa[6], xr[7] * fa[7]);

        float* pi = po + RESN * RESN;   /* channel 1 = imag */
        ((float4*)pi)[0] = make_float4(xi[0] * fa[0], xi[1] * fa[1], xi[2] * fa[2], xi[3] * fa[3]);
        ((float4*)pi)[1] = make_float4(xi[4] * fa[4], xi[5] * fa[5], xi[6] * fa[6], xi[7] * fa[7]);
    }
}

extern "C" void kernel_launch(void* const* d_in, const int* in_sizes, int n_in,
                              void* d_out, int out_size) {
    const float* ksp  = (const float*)d_in[0];
    const float* traj = (const float*)d_in[1];
    float* out = (float*)d_out;

    const int SMEM_ROW = (2 * OSN * LSTR + 2 * OSN) * (int)sizeof(float);          /* 41600 B */
    const int SMEM_COL = SMEM_ROW + RESN * (int)sizeof(float);                     /* 42880 B */

    cudaFuncSetAttribute(row_dft_kernel, cudaFuncAttributeMaxDynamicSharedMemorySize, SMEM_ROW);
    cudaFuncSetAttribute(col_dft_kernel, cudaFuncAttributeMaxDynamicSharedMemorySize, SMEM_COL);

    zero_grid_kernel<<<(NB * OSN * OSN * 2 / 4 + 255) / 256, 256>>>();
    grid_scatter_kernel<<<(NB * MTRAJ + 255) / 256, 256>>>(ksp, traj);
    row_dft_kernel<<<NB * (OSN / GL), OSN, SMEM_ROW>>>();
    col_dft_kernel<<<NB * (RESN / GL), OSN, SMEM_COL>>>(out);
}